// round 6
// baseline (speedup 1.0000x reference)
#include <cuda_runtime.h>
#include <math.h>

#define S_SEG 256
#define T_TOK 512
#define BERT  768
#define POSD  128
#define CAT   (BERT + POSD)   // 896
#define H1    1024
#define NCLS  6
#define NSEG  64
#define KSLICES 16
#define TOKW    16                       // tokens per warp
#define WSLICES (T_TOK / TOKW)           // 32 warp-slices per segment

// Scratch (no allocations allowed) — device globals.
__device__ float g_pacc[WSLICES * S_SEG * BERT];   // unnormalized partial accumulators
__device__ float g_pm[WSLICES * S_SEG];            // partial max
__device__ float g_pd[WSLICES * S_SEG];            // partial denom
__device__ float g_segvec[S_SEG * BERT];
__device__ float g_vecs[NSEG * BERT];
__device__ float g_h1[NSEG * H1];
__device__ float g_h2[NSEG * H1];
__device__ float g_part[KSLICES * NSEG * H1];

// ---------------------------------------------------------------------------
// Kernel 1a: warp-per-token online-softmax pooling. No barriers in main loop.
// 4 launches; launch q covers warp-slices [q*8, q*8+8) of every segment.
// grid (256,1), 256 threads = 8 warps; warp w handles slice q*8+w (16 tokens).
// Lane l owns channels {i*128 + 4l .. +3}, i=0..6 (i=6 -> pos channels).
// ---------------------------------------------------------------------------
__global__ __launch_bounds__(256, 3)
void pool_part_kernel(const float* __restrict__ emb,
                      const float* __restrict__ pos,
                      const float* __restrict__ Wa,
                      const float* __restrict__ ba,
                      int q)
{
    __shared__ float s_wa[CAT];
    const int s    = blockIdx.x;
    const int tid  = threadIdx.x;
    const int wid  = tid >> 5;
    const int lane = tid & 31;

    for (int i = tid; i < CAT; i += 256) s_wa[i] = Wa[i];
    __syncthreads();   // only barrier in the kernel

    const int   slice = q * 8 + wid;
    const int   t0    = slice * TOKW;
    const float bias  = ba[0];

    const float* eb = emb + (size_t)s * T_TOK * BERT;
    const float* pb = pos + (size_t)s * T_TOK * POSD;

    float4 acc[6];
    #pragma unroll
    for (int i = 0; i < 6; i++) acc[i] = make_float4(0.f, 0.f, 0.f, 0.f);
    float m = -1e30f;
    float d = 0.f;

    for (int t = t0; t < t0 + TOKW; t++) {
        float4 x[7];
        #pragma unroll
        for (int i = 0; i < 6; i++)
            x[i] = *(const float4*)(eb + (size_t)t * BERT + i * 128 + lane * 4);
        x[6] = *(const float4*)(pb + (size_t)t * POSD + lane * 4);

        float part = 0.f;
        #pragma unroll
        for (int i = 0; i < 7; i++) {
            const float4 wv = *(const float4*)(s_wa + i * 128 + lane * 4);
            part += x[i].x * wv.x + x[i].y * wv.y + x[i].z * wv.z + x[i].w * wv.w;
        }
        #pragma unroll
        for (int o = 16; o > 0; o >>= 1)
            part += __shfl_xor_sync(0xffffffffu, part, o);

        const float a     = part + bias;
        const float m_new = fmaxf(m, a);
        const float scale = __expf(m - m_new);
        const float p     = __expf(a - m_new);
        d = d * scale + p;
        #pragma unroll
        for (int i = 0; i < 6; i++) {
            acc[i].x = acc[i].x * scale + p * x[i].x;
            acc[i].y = acc[i].y * scale + p * x[i].y;
            acc[i].z = acc[i].z * scale + p * x[i].z;
            acc[i].w = acc[i].w * scale + p * x[i].w;
        }
        m = m_new;
    }

    const int ps = slice * S_SEG + s;
    float* ob = g_pacc + (size_t)ps * BERT;
    #pragma unroll
    for (int i = 0; i < 6; i++)
        *(float4*)(ob + i * 128 + lane * 4) = acc[i];
    if (lane == 0) {
        g_pm[ps] = m;
        g_pd[ps] = d;
    }
}

// ---------------------------------------------------------------------------
// Kernel 1b: merge WSLICES=32 partials per segment (flash-attn merge).
// grid 256, 192 threads (one float4 of 768 channels each).
// ---------------------------------------------------------------------------
__global__ __launch_bounds__(192)
void pool_merge_kernel()
{
    __shared__ float sm[WSLICES], sd[WSLICES], ssc[WSLICES];
    const int s   = blockIdx.x;
    const int tid = threadIdx.x;

    if (tid < WSLICES) {
        sm[tid] = g_pm[tid * S_SEG + s];
        sd[tid] = g_pd[tid * S_SEG + s];
    }
    __syncthreads();

    float M = -1e30f;
    #pragma unroll
    for (int z = 0; z < WSLICES; z++) M = fmaxf(M, sm[z]);

    if (tid < WSLICES) ssc[tid] = __expf(sm[tid] - M);
    __syncthreads();

    float D = 0.f;
    #pragma unroll
    for (int z = 0; z < WSLICES; z++) D += sd[z] * ssc[z];
    const float inv = 1.f / D;

    float4 acc = make_float4(0.f, 0.f, 0.f, 0.f);
    #pragma unroll 4
    for (int z = 0; z < WSLICES; z++) {
        const float  f = ssc[z];
        const float4 p = *(const float4*)(g_pacc + (size_t)(z * S_SEG + s) * BERT + 4 * tid);
        acc.x += f * p.x;
        acc.y += f * p.y;
        acc.z += f * p.z;
        acc.w += f * p.w;
    }
    float4 o = make_float4(acc.x * inv, acc.y * inv, acc.z * inv, acc.w * inv);
    *(float4*)(g_segvec + (size_t)s * BERT + 4 * tid) = o;
}

// ---------------------------------------------------------------------------
// Kernel 2: deterministic segment sum (sorted ids). One CTA per segment g.
// ---------------------------------------------------------------------------
__global__ __launch_bounds__(256)
void segsum_kernel(const int* __restrict__ seg)
{
    __shared__ int sid[S_SEG];
    const int g = blockIdx.x;
    const int tid = threadIdx.x;
    sid[tid] = seg[tid];
    __syncthreads();

    float a0 = 0.f, a1 = 0.f, a2 = 0.f;
    for (int s = 0; s < S_SEG; s++) {
        if (sid[s] == g) {
            const float* r = g_segvec + (size_t)s * BERT;
            a0 += r[tid];
            a1 += r[tid + 256];
            a2 += r[tid + 512];
        }
    }
    g_vecs[g * BERT + tid]       = a0;
    g_vecs[g * BERT + tid + 256] = a1;
    g_vecs[g * BERT + tid + 512] = a2;
}

// ---------------------------------------------------------------------------
// Kernels 3/4: split-K GEMM partials. CTA = 32 rows x 64 cols x CHUNK.
// grid (16 colblocks, 2 rowblocks, KSLICES=16) = 512 CTAs, 128 threads.
// thread = (colquad q -> 4 cols, rowgroup r -> 4 rows): 16 FMA per
// (1 W float4 + 4 broadcast LDS). W read only 2x total.
// ---------------------------------------------------------------------------
template <int K>
__global__ __launch_bounds__(128)
void mlp_splitk_kernel(const float* __restrict__ in, const float* __restrict__ W,
                       float* __restrict__ part)
{
    constexpr int CHUNK = K / KSLICES;   // 48 or 64
    constexpr int TP    = CHUNK + 1;
    __shared__ float tile[32 * TP];

    const int tid   = threadIdx.x;
    const int q     = tid & 15;
    const int r     = tid >> 4;          // 0..7
    const int jbase = blockIdx.x * 64 + q * 4;
    const int rbase = blockIdx.y * 32;
    const int k0    = blockIdx.z * CHUNK;

    for (int e = tid; e < 32 * CHUNK; e += 128) {
        int rr = e / CHUNK;
        int cc = e - rr * CHUNK;
        tile[rr * TP + cc] = in[(size_t)(rbase + rr) * K + k0 + cc];
    }
    __syncthreads();

    float4 acc[4];
    #pragma unroll
    for (int i = 0; i < 4; i++) acc[i] = make_float4(0.f, 0.f, 0.f, 0.f);

    const float* wp = W + (size_t)k0 * H1 + jbase;
    const float* xp = tile + (r * 4) * TP;

    #pragma unroll 4
    for (int kk = 0; kk < CHUNK; kk++) {
        const float4 wv = *(const float4*)(wp + (size_t)kk * H1);
        #pragma unroll
        for (int i = 0; i < 4; i++) {
            const float xv = xp[i * TP + kk];
            acc[i].x += xv * wv.x;
            acc[i].y += xv * wv.y;
            acc[i].z += xv * wv.z;
            acc[i].w += xv * wv.w;
        }
    }

    float* pb = part + (size_t)blockIdx.z * NSEG * H1 + (size_t)(rbase + r * 4) * H1 + jbase;
    #pragma unroll
    for (int i = 0; i < 4; i++)
        *(float4*)(pb + (size_t)i * H1) = acc[i];
}

// Reduce partials + bias + LeakyReLU(0.01). One CTA per row (64), 256 threads.
__global__ __launch_bounds__(256)
void mlp_reduce_kernel(const float* __restrict__ b, float* __restrict__ out)
{
    const int row = blockIdx.x;
    const int c4  = threadIdx.x * 4;
    float4 a = make_float4(0.f, 0.f, 0.f, 0.f);
    #pragma unroll
    for (int z = 0; z < KSLICES; z++) {
        float4 p = *(const float4*)(g_part + (size_t)z * NSEG * H1 + (size_t)row * H1 + c4);
        a.x += p.x; a.y += p.y; a.z += p.z; a.w += p.w;
    }
    const float4 bb = *(const float4*)(b + c4);
    float4 o;
    o.x = a.x + bb.x; o.x = o.x > 0.f ? o.x : 0.01f * o.x;
    o.y = a.y + bb.y; o.y = o.y > 0.f ? o.y : 0.01f * o.y;
    o.z = a.z + bb.z; o.z = o.z > 0.f ? o.z : 0.01f * o.z;
    o.w = a.w + bb.w; o.w = o.w > 0.f ? o.w : 0.01f * o.w;
    *(float4*)(out + (size_t)row * H1 + c4) = o;
}

// ---------------------------------------------------------------------------
// Kernel 5: head (64,1024)@(1024,6) + bias, sigmoid. One warp per segment.
// ---------------------------------------------------------------------------
__global__ __launch_bounds__(32)
void head_kernel(const float* __restrict__ W3, const float* __restrict__ b3,
                 float* __restrict__ out)
{
    const int g    = blockIdx.x;
    const int lane = threadIdx.x;
    float p[NCLS] = {0.f, 0.f, 0.f, 0.f, 0.f, 0.f};

    for (int k = lane; k < H1; k += 32) {
        float x = g_h2[(size_t)g * H1 + k];
        #pragma unroll
        for (int j = 0; j < NCLS; j++)
            p[j] += x * W3[k * NCLS + j];
    }
    #pragma unroll
    for (int j = 0; j < NCLS; j++) {
        #pragma unroll
        for (int o = 16; o > 0; o >>= 1)
            p[j] += __shfl_xor_sync(0xffffffffu, p[j], o);
    }
    if (lane < NCLS) {
        float v = p[lane] + b3[lane];
        out[g * NCLS + lane] = 1.f / (1.f + expf(-v));
    }
}

// ---------------------------------------------------------------------------
extern "C" void kernel_launch(void* const* d_in, const int* in_sizes, int n_in,
                              void* d_out, int out_size)
{
    (void)in_sizes; (void)n_in; (void)out_size;
    const float* emb = (const float*)d_in[0];
    const float* pos = (const float*)d_in[1];
    const float* Wa  = (const float*)d_in[2];
    const float* ba  = (const float*)d_in[3];
    const float* W1  = (const float*)d_in[4];
    const float* b1  = (const float*)d_in[5];
    const float* W2  = (const float*)d_in[6];
    const float* b2  = (const float*)d_in[7];
    const float* W3  = (const float*)d_in[8];
    const float* b3  = (const float*)d_in[9];
    const int*   seg = (const int*)d_in[10];
    float* out = (float*)d_out;

    void *p_vecs = nullptr, *p_h1 = nullptr, *p_h2 = nullptr, *p_part = nullptr;
    cudaGetSymbolAddress(&p_vecs, g_vecs);
    cudaGetSymbolAddress(&p_h1, g_h1);
    cudaGetSymbolAddress(&p_h2, g_h2);
    cudaGetSymbolAddress(&p_part, g_part);

    // Pool: 4 launches over warp-slice ranges; launch #3 (ncu capture slot)
    // is a pool slice so pool metrics stay visible.
    pool_part_kernel<<<S_SEG, 256>>>(emb, pos, Wa, ba, 0);
    pool_part_kernel<<<S_SEG, 256>>>(emb, pos, Wa, ba, 1);
    pool_part_kernel<<<S_SEG, 256>>>(emb, pos, Wa, ba, 2);
    pool_part_kernel<<<S_SEG, 256>>>(emb, pos, Wa, ba, 3);

    pool_merge_kernel<<<S_SEG, 192>>>();
    segsum_kernel<<<NSEG, 256>>>(seg);

    mlp_splitk_kernel<BERT><<<dim3(16, 2, KSLICES), 128>>>(
        (const float*)p_vecs, W1, (float*)p_part);
    mlp_reduce_kernel<<<NSEG, 256>>>(b1, (float*)p_h1);

    mlp_splitk_kernel<H1><<<dim3(16, 2, KSLICES), 128>>>(
        (const float*)p_h1, W2, (float*)p_part);
    mlp_reduce_kernel<<<NSEG, 256>>>(b2, (float*)p_h2);

    head_kernel<<<NSEG, 32>>>(W3, b3, out);
}

// round 7
// speedup vs baseline: 1.1256x; 1.1256x over previous
#include <cuda_runtime.h>
#include <math.h>

#define S_SEG 256
#define T_TOK 512
#define BERT  768
#define POSD  128
#define CAT   (BERT + POSD)   // 896
#define H1    1024
#define NCLS  6
#define NSEG  64
#define KSLICES 16
#define TOKW    16                       // tokens per warp
#define WSLICES (T_TOK / TOKW)           // 32 warp-slices per segment

// Scratch (no allocations allowed) — device globals.
__device__ float g_pacc[WSLICES * S_SEG * BERT];   // unnormalized partial accumulators
__device__ float g_pm[WSLICES * S_SEG];            // partial max
__device__ float g_pd[WSLICES * S_SEG];            // partial denom
__device__ float g_segvec[S_SEG * BERT];
__device__ float g_vecs[NSEG * BERT];
__device__ float g_h1[NSEG * H1];
__device__ float g_h2[NSEG * H1];
__device__ float g_part[KSLICES * NSEG * H1];

// ---------------------------------------------------------------------------
// Kernel 1a: warp-per-token online-softmax pooling. Single launch,
// grid (256, 4) = 1024 CTAs. CTA (s, q): its 8 warps handle warp-slices
// q*8+wid of segment s (16 tokens each). No barriers in the main loop.
// Lane l owns channels {i*128 + 4l .. +3}, i=0..6 (i=6 -> pos channels).
// ---------------------------------------------------------------------------
__global__ __launch_bounds__(256, 3)
void pool_part_kernel(const float* __restrict__ emb,
                      const float* __restrict__ pos,
                      const float* __restrict__ Wa,
                      const float* __restrict__ ba)
{
    __shared__ float s_wa[CAT];
    const int s    = blockIdx.x;
    const int q    = blockIdx.y;
    const int tid  = threadIdx.x;
    const int wid  = tid >> 5;
    const int lane = tid & 31;

    for (int i = tid; i < CAT; i += 256) s_wa[i] = Wa[i];
    __syncthreads();   // only barrier in the kernel

    const int   slice = q * 8 + wid;
    const int   t0    = slice * TOKW;
    const float bias  = ba[0];

    const float* eb = emb + (size_t)s * T_TOK * BERT;
    const float* pb = pos + (size_t)s * T_TOK * POSD;

    float4 acc[6];
    #pragma unroll
    for (int i = 0; i < 6; i++) acc[i] = make_float4(0.f, 0.f, 0.f, 0.f);
    float m = -1e30f;
    float d = 0.f;

    for (int t = t0; t < t0 + TOKW; t++) {
        float4 x[7];
        #pragma unroll
        for (int i = 0; i < 6; i++)
            x[i] = *(const float4*)(eb + (size_t)t * BERT + i * 128 + lane * 4);
        x[6] = *(const float4*)(pb + (size_t)t * POSD + lane * 4);

        float part = 0.f;
        #pragma unroll
        for (int i = 0; i < 7; i++) {
            const float4 wv = *(const float4*)(s_wa + i * 128 + lane * 4);
            part += x[i].x * wv.x + x[i].y * wv.y + x[i].z * wv.z + x[i].w * wv.w;
        }
        #pragma unroll
        for (int o = 16; o > 0; o >>= 1)
            part += __shfl_xor_sync(0xffffffffu, part, o);

        const float a     = part + bias;
        const float m_new = fmaxf(m, a);
        const float scale = __expf(m - m_new);
        const float p     = __expf(a - m_new);
        d = d * scale + p;
        #pragma unroll
        for (int i = 0; i < 6; i++) {
            acc[i].x = acc[i].x * scale + p * x[i].x;
            acc[i].y = acc[i].y * scale + p * x[i].y;
            acc[i].z = acc[i].z * scale + p * x[i].z;
            acc[i].w = acc[i].w * scale + p * x[i].w;
        }
        m = m_new;
    }

    const int ps = slice * S_SEG + s;
    float* ob = g_pacc + (size_t)ps * BERT;
    #pragma unroll
    for (int i = 0; i < 6; i++)
        *(float4*)(ob + i * 128 + lane * 4) = acc[i];
    if (lane == 0) {
        g_pm[ps] = m;
        g_pd[ps] = d;
    }
}

// ---------------------------------------------------------------------------
// Kernel 1b: merge WSLICES=32 partials per segment (flash-attn merge).
// grid 256, 192 threads (one float4 of 768 channels each).
// ---------------------------------------------------------------------------
__global__ __launch_bounds__(192)
void pool_merge_kernel()
{
    __shared__ float sm[WSLICES], sd[WSLICES], ssc[WSLICES];
    const int s   = blockIdx.x;
    const int tid = threadIdx.x;

    if (tid < WSLICES) {
        sm[tid] = g_pm[tid * S_SEG + s];
        sd[tid] = g_pd[tid * S_SEG + s];
    }
    __syncthreads();

    float M = -1e30f;
    #pragma unroll
    for (int z = 0; z < WSLICES; z++) M = fmaxf(M, sm[z]);

    if (tid < WSLICES) ssc[tid] = __expf(sm[tid] - M);
    __syncthreads();

    float D = 0.f;
    #pragma unroll
    for (int z = 0; z < WSLICES; z++) D += sd[z] * ssc[z];
    const float inv = 1.f / D;

    float4 acc = make_float4(0.f, 0.f, 0.f, 0.f);
    #pragma unroll 4
    for (int z = 0; z < WSLICES; z++) {
        const float  f = ssc[z];
        const float4 p = *(const float4*)(g_pacc + (size_t)(z * S_SEG + s) * BERT + 4 * tid);
        acc.x += f * p.x;
        acc.y += f * p.y;
        acc.z += f * p.z;
        acc.w += f * p.w;
    }
    float4 o = make_float4(acc.x * inv, acc.y * inv, acc.z * inv, acc.w * inv);
    *(float4*)(g_segvec + (size_t)s * BERT + 4 * tid) = o;
}

// ---------------------------------------------------------------------------
// Kernel 2: deterministic segment sum (sorted ids). One CTA per segment g.
// ---------------------------------------------------------------------------
__global__ __launch_bounds__(256)
void segsum_kernel(const int* __restrict__ seg)
{
    __shared__ int sid[S_SEG];
    const int g = blockIdx.x;
    const int tid = threadIdx.x;
    sid[tid] = seg[tid];
    __syncthreads();

    float a0 = 0.f, a1 = 0.f, a2 = 0.f;
    for (int s = 0; s < S_SEG; s++) {
        if (sid[s] == g) {
            const float* r = g_segvec + (size_t)s * BERT;
            a0 += r[tid];
            a1 += r[tid + 256];
            a2 += r[tid + 512];
        }
    }
    g_vecs[g * BERT + tid]       = a0;
    g_vecs[g * BERT + tid + 256] = a1;
    g_vecs[g * BERT + tid + 512] = a2;
}

// ---------------------------------------------------------------------------
// Kernels 3/4: split-K GEMM partials. CTA = 32 rows x 64 cols x CHUNK.
// grid (16 colblocks, 2 rowblocks, KSLICES=16) = 512 CTAs, 128 threads.
// ---------------------------------------------------------------------------
template <int K>
__global__ __launch_bounds__(128)
void mlp_splitk_kernel(const float* __restrict__ in, const float* __restrict__ W,
                       float* __restrict__ part)
{
    constexpr int CHUNK = K / KSLICES;   // 48 or 64
    constexpr int TP    = CHUNK + 1;
    __shared__ float tile[32 * TP];

    const int tid   = threadIdx.x;
    const int q     = tid & 15;
    const int r     = tid >> 4;          // 0..7
    const int jbase = blockIdx.x * 64 + q * 4;
    const int rbase = blockIdx.y * 32;
    const int k0    = blockIdx.z * CHUNK;

    for (int e = tid; e < 32 * CHUNK; e += 128) {
        int rr = e / CHUNK;
        int cc = e - rr * CHUNK;
        tile[rr * TP + cc] = in[(size_t)(rbase + rr) * K + k0 + cc];
    }
    __syncthreads();

    float4 acc[4];
    #pragma unroll
    for (int i = 0; i < 4; i++) acc[i] = make_float4(0.f, 0.f, 0.f, 0.f);

    const float* wp = W + (size_t)k0 * H1 + jbase;
    const float* xp = tile + (r * 4) * TP;

    #pragma unroll 4
    for (int kk = 0; kk < CHUNK; kk++) {
        const float4 wv = *(const float4*)(wp + (size_t)kk * H1);
        #pragma unroll
        for (int i = 0; i < 4; i++) {
            const float xv = xp[i * TP + kk];
            acc[i].x += xv * wv.x;
            acc[i].y += xv * wv.y;
            acc[i].z += xv * wv.z;
            acc[i].w += xv * wv.w;
        }
    }

    float* pb = part + (size_t)blockIdx.z * NSEG * H1 + (size_t)(rbase + r * 4) * H1 + jbase;
    #pragma unroll
    for (int i = 0; i < 4; i++)
        *(float4*)(pb + (size_t)i * H1) = acc[i];
}

// Reduce partials + bias + LeakyReLU(0.01). One CTA per row (64), 256 threads.
__global__ __launch_bounds__(256)
void mlp_reduce_kernel(const float* __restrict__ b, float* __restrict__ out)
{
    const int row = blockIdx.x;
    const int c4  = threadIdx.x * 4;
    float4 a = make_float4(0.f, 0.f, 0.f, 0.f);
    #pragma unroll
    for (int z = 0; z < KSLICES; z++) {
        float4 p = *(const float4*)(g_part + (size_t)z * NSEG * H1 + (size_t)row * H1 + c4);
        a.x += p.x; a.y += p.y; a.z += p.z; a.w += p.w;
    }
    const float4 bb = *(const float4*)(b + c4);
    float4 o;
    o.x = a.x + bb.x; o.x = o.x > 0.f ? o.x : 0.01f * o.x;
    o.y = a.y + bb.y; o.y = o.y > 0.f ? o.y : 0.01f * o.y;
    o.z = a.z + bb.z; o.z = o.z > 0.f ? o.z : 0.01f * o.z;
    o.w = a.w + bb.w; o.w = o.w > 0.f ? o.w : 0.01f * o.w;
    *(float4*)(out + (size_t)row * H1 + c4) = o;
}

// ---------------------------------------------------------------------------
// Kernel 5: head (64,1024)@(1024,6) + bias, sigmoid. One warp per segment.
// ---------------------------------------------------------------------------
__global__ __launch_bounds__(32)
void head_kernel(const float* __restrict__ W3, const float* __restrict__ b3,
                 float* __restrict__ out)
{
    const int g    = blockIdx.x;
    const int lane = threadIdx.x;
    float p[NCLS] = {0.f, 0.f, 0.f, 0.f, 0.f, 0.f};

    for (int k = lane; k < H1; k += 32) {
        float x = g_h2[(size_t)g * H1 + k];
        #pragma unroll
        for (int j = 0; j < NCLS; j++)
            p[j] += x * W3[k * NCLS + j];
    }
    #pragma unroll
    for (int j = 0; j < NCLS; j++) {
        #pragma unroll
        for (int o = 16; o > 0; o >>= 1)
            p[j] += __shfl_xor_sync(0xffffffffu, p[j], o);
    }
    if (lane < NCLS) {
        float v = p[lane] + b3[lane];
        out[g * NCLS + lane] = 1.f / (1.f + expf(-v));
    }
}

// ---------------------------------------------------------------------------
extern "C" void kernel_launch(void* const* d_in, const int* in_sizes, int n_in,
                              void* d_out, int out_size)
{
    (void)in_sizes; (void)n_in; (void)out_size;
    const float* emb = (const float*)d_in[0];
    const float* pos = (const float*)d_in[1];
    const float* Wa  = (const float*)d_in[2];
    const float* ba  = (const float*)d_in[3];
    const float* W1  = (const float*)d_in[4];
    const float* b1  = (const float*)d_in[5];
    const float* W2  = (const float*)d_in[6];
    const float* b2  = (const float*)d_in[7];
    const float* W3  = (const float*)d_in[8];
    const float* b3  = (const float*)d_in[9];
    const int*   seg = (const int*)d_in[10];
    float* out = (float*)d_out;

    void *p_vecs = nullptr, *p_h1 = nullptr, *p_h2 = nullptr, *p_part = nullptr;
    cudaGetSymbolAddress(&p_vecs, g_vecs);
    cudaGetSymbolAddress(&p_h1, g_h1);
    cudaGetSymbolAddress(&p_h2, g_h2);
    cudaGetSymbolAddress(&p_part, g_part);

    pool_part_kernel<<<dim3(S_SEG, 4), 256>>>(emb, pos, Wa, ba);
    pool_merge_kernel<<<S_SEG, 192>>>();
    segsum_kernel<<<NSEG, 256>>>(seg);

    mlp_splitk_kernel<BERT><<<dim3(16, 2, KSLICES), 128>>>(
        (const float*)p_vecs, W1, (float*)p_part);
    mlp_reduce_kernel<<<NSEG, 256>>>(b1, (float*)p_h1);

    mlp_splitk_kernel<H1><<<dim3(16, 2, KSLICES), 128>>>(
        (const float*)p_h1, W2, (float*)p_part);
    mlp_reduce_kernel<<<NSEG, 256>>>(b2, (float*)p_h2);

    head_kernel<<<NSEG, 32>>>(W3, b3, out);
}

// round 8
// speedup vs baseline: 1.2409x; 1.1024x over previous
#include <cuda_runtime.h>
#include <math.h>

#define S_SEG 256
#define T_TOK 512
#define BERT  768
#define POSD  128
#define CAT   (BERT + POSD)   // 896
#define H1    1024
#define NCLS  6
#define NSEG  64
#define KSLICES 16
#define TOKW    16                       // tokens per warp
#define WSLICES (T_TOK / TOKW)           // 32 warp-slices per segment

// Scratch (no allocations allowed) — device globals.
__device__ float g_pacc[WSLICES * S_SEG * BERT];   // unnormalized partial accumulators
__device__ float g_pm[WSLICES * S_SEG];            // partial max
__device__ float g_pd[WSLICES * S_SEG];            // partial denom
__device__ float g_segvec[S_SEG * BERT];
__device__ float g_vecs[NSEG * BERT];
__device__ float g_h1[NSEG * H1];
__device__ float g_h2[NSEG * H1];
__device__ float g_part[KSLICES * NSEG * H1];

// ---------------------------------------------------------------------------
// Kernel 1a: warp-per-token online-softmax pooling. Single launch,
// grid (256, 4) = 1024 CTAs. CTA (s, q): its 8 warps handle warp-slices
// q*8+wid of segment s (16 tokens each). No barriers in the main loop.
// ---------------------------------------------------------------------------
__global__ __launch_bounds__(256, 3)
void pool_part_kernel(const float* __restrict__ emb,
                      const float* __restrict__ pos,
                      const float* __restrict__ Wa,
                      const float* __restrict__ ba)
{
    __shared__ float s_wa[CAT];
    const int s    = blockIdx.x;
    const int q    = blockIdx.y;
    const int tid  = threadIdx.x;
    const int wid  = tid >> 5;
    const int lane = tid & 31;

    for (int i = tid; i < CAT; i += 256) s_wa[i] = Wa[i];
    __syncthreads();   // only barrier in the kernel

    const int   slice = q * 8 + wid;
    const int   t0    = slice * TOKW;
    const float bias  = ba[0];

    const float* eb = emb + (size_t)s * T_TOK * BERT;
    const float* pb = pos + (size_t)s * T_TOK * POSD;

    float4 acc[6];
    #pragma unroll
    for (int i = 0; i < 6; i++) acc[i] = make_float4(0.f, 0.f, 0.f, 0.f);
    float m = -1e30f;
    float d = 0.f;

    for (int t = t0; t < t0 + TOKW; t++) {
        float4 x[7];
        #pragma unroll
        for (int i = 0; i < 6; i++)
            x[i] = *(const float4*)(eb + (size_t)t * BERT + i * 128 + lane * 4);
        x[6] = *(const float4*)(pb + (size_t)t * POSD + lane * 4);

        float part = 0.f;
        #pragma unroll
        for (int i = 0; i < 7; i++) {
            const float4 wv = *(const float4*)(s_wa + i * 128 + lane * 4);
            part += x[i].x * wv.x + x[i].y * wv.y + x[i].z * wv.z + x[i].w * wv.w;
        }
        #pragma unroll
        for (int o = 16; o > 0; o >>= 1)
            part += __shfl_xor_sync(0xffffffffu, part, o);

        const float a     = part + bias;
        const float m_new = fmaxf(m, a);
        const float scale = __expf(m - m_new);
        const float p     = __expf(a - m_new);
        d = d * scale + p;
        #pragma unroll
        for (int i = 0; i < 6; i++) {
            acc[i].x = acc[i].x * scale + p * x[i].x;
            acc[i].y = acc[i].y * scale + p * x[i].y;
            acc[i].z = acc[i].z * scale + p * x[i].z;
            acc[i].w = acc[i].w * scale + p * x[i].w;
        }
        m = m_new;
    }

    const int ps = slice * S_SEG + s;
    float* ob = g_pacc + (size_t)ps * BERT;
    #pragma unroll
    for (int i = 0; i < 6; i++)
        *(float4*)(ob + i * 128 + lane * 4) = acc[i];
    if (lane == 0) {
        g_pm[ps] = m;
        g_pd[ps] = d;
    }
}

// ---------------------------------------------------------------------------
// Kernel 1b: merge WSLICES=32 partials per segment (flash-attn merge).
// ---------------------------------------------------------------------------
__global__ __launch_bounds__(192)
void pool_merge_kernel()
{
    __shared__ float sm[WSLICES], sd[WSLICES], ssc[WSLICES];
    const int s   = blockIdx.x;
    const int tid = threadIdx.x;

    if (tid < WSLICES) {
        sm[tid] = g_pm[tid * S_SEG + s];
        sd[tid] = g_pd[tid * S_SEG + s];
    }
    __syncthreads();

    float M = -1e30f;
    #pragma unroll
    for (int z = 0; z < WSLICES; z++) M = fmaxf(M, sm[z]);

    if (tid < WSLICES) ssc[tid] = __expf(sm[tid] - M);
    __syncthreads();

    float D = 0.f;
    #pragma unroll
    for (int z = 0; z < WSLICES; z++) D += sd[z] * ssc[z];
    const float inv = 1.f / D;

    float4 acc = make_float4(0.f, 0.f, 0.f, 0.f);
    #pragma unroll 4
    for (int z = 0; z < WSLICES; z++) {
        const float  f = ssc[z];
        const float4 p = *(const float4*)(g_pacc + (size_t)(z * S_SEG + s) * BERT + 4 * tid);
        acc.x += f * p.x;
        acc.y += f * p.y;
        acc.z += f * p.z;
        acc.w += f * p.w;
    }
    float4 o = make_float4(acc.x * inv, acc.y * inv, acc.z * inv, acc.w * inv);
    *(float4*)(g_segvec + (size_t)s * BERT + 4 * tid) = o;
}

// ---------------------------------------------------------------------------
// Kernel 2: deterministic segment sum (sorted ids). One CTA per segment g.
// ---------------------------------------------------------------------------
__global__ __launch_bounds__(256)
void segsum_kernel(const int* __restrict__ seg)
{
    __shared__ int sid[S_SEG];
    const int g = blockIdx.x;
    const int tid = threadIdx.x;
    sid[tid] = seg[tid];
    __syncthreads();

    float a0 = 0.f, a1 = 0.f, a2 = 0.f;
    for (int s = 0; s < S_SEG; s++) {
        if (sid[s] == g) {
            const float* r = g_segvec + (size_t)s * BERT;
            a0 += r[tid];
            a1 += r[tid + 256];
            a2 += r[tid + 512];
        }
    }
    g_vecs[g * BERT + tid]       = a0;
    g_vecs[g * BERT + tid + 256] = a1;
    g_vecs[g * BERT + tid + 512] = a2;
}

// ---------------------------------------------------------------------------
// Kernels 3/4: split-K GEMM partials with explicit 8-deep register
// double-buffering of W loads. CTA = 32 rows x 64 cols x CHUNK.
// grid (16 colblocks, 2 rowblocks, KSLICES=16) = 512 CTAs, 128 threads.
// thread = (colquad q -> 4 cols, rowgroup r -> 4 rows).
// ---------------------------------------------------------------------------
template <int K>
__global__ __launch_bounds__(128)
void mlp_splitk_kernel(const float* __restrict__ in, const float* __restrict__ W,
                       float* __restrict__ part)
{
    constexpr int CHUNK = K / KSLICES;   // 48 or 64  (multiples of 8)
    constexpr int NB    = CHUNK / 8;     // 6 or 8 batches
    constexpr int TP    = CHUNK + 1;
    __shared__ float tile[32 * TP];

    const int tid   = threadIdx.x;
    const int q     = tid & 15;
    const int r     = tid >> 4;          // 0..7
    const int jbase = blockIdx.x * 64 + q * 4;
    const int rbase = blockIdx.y * 32;
    const int k0    = blockIdx.z * CHUNK;

    for (int e = tid; e < 32 * CHUNK; e += 128) {
        int rr = e / CHUNK;
        int cc = e - rr * CHUNK;
        tile[rr * TP + cc] = in[(size_t)(rbase + rr) * K + k0 + cc];
    }
    __syncthreads();

    float4 acc[4];
    #pragma unroll
    for (int i = 0; i < 4; i++) acc[i] = make_float4(0.f, 0.f, 0.f, 0.f);

    const float* wp = W + (size_t)k0 * H1 + jbase;
    const float* xp = tile + (r * 4) * TP;

    // prologue: first batch of 8 W loads in flight
    float4 wbuf[8];
    #pragma unroll
    for (int i = 0; i < 8; i++)
        wbuf[i] = *(const float4*)(wp + (size_t)i * H1);

    #pragma unroll
    for (int kb = 0; kb < NB; kb++) {
        float4 wnext[8];
        if (kb + 1 < NB) {
            #pragma unroll
            for (int i = 0; i < 8; i++)
                wnext[i] = *(const float4*)(wp + (size_t)((kb + 1) * 8 + i) * H1);
        }
        #pragma unroll
        for (int i = 0; i < 8; i++) {
            const int kk = kb * 8 + i;
            #pragma unroll
            for (int rr = 0; rr < 4; rr++) {
                const float xv = xp[rr * TP + kk];
                acc[rr].x += xv * wbuf[i].x;
                acc[rr].y += xv * wbuf[i].y;
                acc[rr].z += xv * wbuf[i].z;
                acc[rr].w += xv * wbuf[i].w;
            }
        }
        if (kb + 1 < NB) {
            #pragma unroll
            for (int i = 0; i < 8; i++) wbuf[i] = wnext[i];
        }
    }

    float* pb = part + (size_t)blockIdx.z * NSEG * H1 + (size_t)(rbase + r * 4) * H1 + jbase;
    #pragma unroll
    for (int i = 0; i < 4; i++)
        *(float4*)(pb + (size_t)i * H1) = acc[i];
}

// Reduce partials + bias + LeakyReLU(0.01). grid 256 (quarter-row per CTA),
// 256 threads, one scalar column each. 16 independent loads per thread.
__global__ __launch_bounds__(256)
void mlp_reduce_kernel(const float* __restrict__ b, float* __restrict__ out)
{
    const int row = blockIdx.x >> 2;
    const int col = (blockIdx.x & 3) * 256 + threadIdx.x;
    const size_t off = (size_t)row * H1 + col;

    float a = 0.f;
    #pragma unroll
    for (int z = 0; z < KSLICES; z++)
        a += g_part[(size_t)z * NSEG * H1 + off];

    a += b[col];
    out[off] = a > 0.f ? a : 0.01f * a;
}

// ---------------------------------------------------------------------------
// Kernel 5: head (64,1024)@(1024,6) + bias, sigmoid. One warp per segment.
// ---------------------------------------------------------------------------
__global__ __launch_bounds__(32)
void head_kernel(const float* __restrict__ W3, const float* __restrict__ b3,
                 float* __restrict__ out)
{
    const int g    = blockIdx.x;
    const int lane = threadIdx.x;
    float p[NCLS] = {0.f, 0.f, 0.f, 0.f, 0.f, 0.f};

    for (int k = lane; k < H1; k += 32) {
        float x = g_h2[(size_t)g * H1 + k];
        #pragma unroll
        for (int j = 0; j < NCLS; j++)
            p[j] += x * W3[k * NCLS + j];
    }
    #pragma unroll
    for (int j = 0; j < NCLS; j++) {
        #pragma unroll
        for (int o = 16; o > 0; o >>= 1)
            p[j] += __shfl_xor_sync(0xffffffffu, p[j], o);
    }
    if (lane < NCLS) {
        float v = p[lane] + b3[lane];
        out[g * NCLS + lane] = 1.f / (1.f + expf(-v));
    }
}

// ---------------------------------------------------------------------------
extern "C" void kernel_launch(void* const* d_in, const int* in_sizes, int n_in,
                              void* d_out, int out_size)
{
    (void)in_sizes; (void)n_in; (void)out_size;
    const float* emb = (const float*)d_in[0];
    const float* pos = (const float*)d_in[1];
    const float* Wa  = (const float*)d_in[2];
    const float* ba  = (const float*)d_in[3];
    const float* W1  = (const float*)d_in[4];
    const float* b1  = (const float*)d_in[5];
    const float* W2  = (const float*)d_in[6];
    const float* b2  = (const float*)d_in[7];
    const float* W3  = (const float*)d_in[8];
    const float* b3  = (const float*)d_in[9];
    const int*   seg = (const int*)d_in[10];
    float* out = (float*)d_out;

    void *p_vecs = nullptr, *p_h1 = nullptr, *p_h2 = nullptr, *p_part = nullptr;
    cudaGetSymbolAddress(&p_vecs, g_vecs);
    cudaGetSymbolAddress(&p_h1, g_h1);
    cudaGetSymbolAddress(&p_h2, g_h2);
    cudaGetSymbolAddress(&p_part, g_part);

    pool_part_kernel<<<dim3(S_SEG, 4), 256>>>(emb, pos, Wa, ba);
    pool_merge_kernel<<<S_SEG, 192>>>();
    segsum_kernel<<<NSEG, 256>>>(seg);

    mlp_splitk_kernel<BERT><<<dim3(16, 2, KSLICES), 128>>>(
        (const float*)p_vecs, W1, (float*)p_part);
    mlp_reduce_kernel<<<NSEG * 4, 256>>>(b1, (float*)p_h1);

    mlp_splitk_kernel<H1><<<dim3(16, 2, KSLICES), 128>>>(
        (const float*)p_h1, W2, (float*)p_part);
    mlp_reduce_kernel<<<NSEG * 4, 256>>>(b2, (float*)p_h2);

    head_kernel<<<NSEG, 32>>>(W3, b3, out);
}

// round 9
// speedup vs baseline: 1.4314x; 1.1536x over previous
#include <cuda_runtime.h>
#include <math.h>

#define S_SEG 256
#define T_TOK 512
#define BERT  768
#define POSD  128
#define CAT   (BERT + POSD)   // 896
#define H1    1024
#define NCLS  6
#define NSEG  64
#define KSLICES 32
#define TOKW    16                       // tokens per warp
#define WSLICES (T_TOK / TOKW)           // 32 warp-slices per segment

// Scratch (no allocations allowed) — device globals.
__device__ float g_pacc[WSLICES * S_SEG * BERT];   // unnormalized partial accumulators
__device__ float g_pm[WSLICES * S_SEG];            // partial max
__device__ float g_pd[WSLICES * S_SEG];            // partial denom
__device__ float g_segvec[S_SEG * BERT];
__device__ float g_vecs[NSEG * BERT];
__device__ float g_h1[NSEG * H1];
__device__ float g_h2[NSEG * H1];
__device__ float g_part[KSLICES * NSEG * H1];

// ---------------------------------------------------------------------------
// Kernel 1a: warp-per-token online-softmax pooling with 1-token software
// pipeline (loads for t+1 issued before computing t -> no RAW stall).
// grid (256, 4) = 1024 CTAs. Warp (s, q*8+wid) handles 16 tokens.
// ---------------------------------------------------------------------------
__global__ __launch_bounds__(256, 2)
void pool_part_kernel(const float* __restrict__ emb,
                      const float* __restrict__ pos,
                      const float* __restrict__ Wa,
                      const float* __restrict__ ba)
{
    __shared__ float s_wa[CAT];
    const int s    = blockIdx.x;
    const int q    = blockIdx.y;
    const int tid  = threadIdx.x;
    const int wid  = tid >> 5;
    const int lane = tid & 31;

    for (int i = tid; i < CAT; i += 256) s_wa[i] = Wa[i];
    __syncthreads();   // only barrier in the kernel

    const int   slice = q * 8 + wid;
    const int   t0    = slice * TOKW;
    const float bias  = ba[0];

    const float* eb = emb + (size_t)s * T_TOK * BERT;
    const float* pb = pos + (size_t)s * T_TOK * POSD;

    float4 acc[6];
    #pragma unroll
    for (int i = 0; i < 6; i++) acc[i] = make_float4(0.f, 0.f, 0.f, 0.f);
    float m = -1e30f;
    float d = 0.f;

    // prologue: load token t0
    float4 xc[7];
    #pragma unroll
    for (int i = 0; i < 6; i++)
        xc[i] = *(const float4*)(eb + (size_t)t0 * BERT + i * 128 + lane * 4);
    xc[6] = *(const float4*)(pb + (size_t)t0 * POSD + lane * 4);

    #pragma unroll 1
    for (int j = 0; j < TOKW; j++) {
        const int  t    = t0 + j;
        const bool more = (j + 1 < TOKW);

        // issue next token's loads before computing current
        float4 xn[7];
        if (more) {
            #pragma unroll
            for (int i = 0; i < 6; i++)
                xn[i] = *(const float4*)(eb + (size_t)(t + 1) * BERT + i * 128 + lane * 4);
            xn[6] = *(const float4*)(pb + (size_t)(t + 1) * POSD + lane * 4);
        }

        float part = 0.f;
        #pragma unroll
        for (int i = 0; i < 7; i++) {
            const float4 wv = *(const float4*)(s_wa + i * 128 + lane * 4);
            part += xc[i].x * wv.x + xc[i].y * wv.y + xc[i].z * wv.z + xc[i].w * wv.w;
        }
        #pragma unroll
        for (int o = 16; o > 0; o >>= 1)
            part += __shfl_xor_sync(0xffffffffu, part, o);

        const float a     = part + bias;
        const float m_new = fmaxf(m, a);
        const float scale = __expf(m - m_new);
        const float p     = __expf(a - m_new);
        d = d * scale + p;
        #pragma unroll
        for (int i = 0; i < 6; i++) {
            acc[i].x = acc[i].x * scale + p * xc[i].x;
            acc[i].y = acc[i].y * scale + p * xc[i].y;
            acc[i].z = acc[i].z * scale + p * xc[i].z;
            acc[i].w = acc[i].w * scale + p * xc[i].w;
        }
        m = m_new;

        if (more) {
            #pragma unroll
            for (int i = 0; i < 7; i++) xc[i] = xn[i];
        }
    }

    const int ps = slice * S_SEG + s;
    float* ob = g_pacc + (size_t)ps * BERT;
    #pragma unroll
    for (int i = 0; i < 6; i++)
        *(float4*)(ob + i * 128 + lane * 4) = acc[i];
    if (lane == 0) {
        g_pm[ps] = m;
        g_pd[ps] = d;
    }
}

// ---------------------------------------------------------------------------
// Kernel 1b: merge WSLICES=32 partials per segment (flash-attn merge).
// ---------------------------------------------------------------------------
__global__ __launch_bounds__(192)
void pool_merge_kernel()
{
    __shared__ float sm[WSLICES], sd[WSLICES], ssc[WSLICES];
    const int s   = blockIdx.x;
    const int tid = threadIdx.x;

    if (tid < WSLICES) {
        sm[tid] = g_pm[tid * S_SEG + s];
        sd[tid] = g_pd[tid * S_SEG + s];
    }
    __syncthreads();

    float M = -1e30f;
    #pragma unroll
    for (int z = 0; z < WSLICES; z++) M = fmaxf(M, sm[z]);

    if (tid < WSLICES) ssc[tid] = __expf(sm[tid] - M);
    __syncthreads();

    float D = 0.f;
    #pragma unroll
    for (int z = 0; z < WSLICES; z++) D += sd[z] * ssc[z];
    const float inv = 1.f / D;

    float4 acc = make_float4(0.f, 0.f, 0.f, 0.f);
    #pragma unroll 4
    for (int z = 0; z < WSLICES; z++) {
        const float  f = ssc[z];
        const float4 p = *(const float4*)(g_pacc + (size_t)(z * S_SEG + s) * BERT + 4 * tid);
        acc.x += f * p.x;
        acc.y += f * p.y;
        acc.z += f * p.z;
        acc.w += f * p.w;
    }
    float4 o = make_float4(acc.x * inv, acc.y * inv, acc.z * inv, acc.w * inv);
    *(float4*)(g_segvec + (size_t)s * BERT + 4 * tid) = o;
}

// ---------------------------------------------------------------------------
// Kernel 2: deterministic segment sum (sorted ids). One CTA per segment g.
// ---------------------------------------------------------------------------
__global__ __launch_bounds__(256)
void segsum_kernel(const int* __restrict__ seg)
{
    __shared__ int sid[S_SEG];
    const int g = blockIdx.x;
    const int tid = threadIdx.x;
    sid[tid] = seg[tid];
    __syncthreads();

    float a0 = 0.f, a1 = 0.f, a2 = 0.f;
    for (int s = 0; s < S_SEG; s++) {
        if (sid[s] == g) {
            const float* r = g_segvec + (size_t)s * BERT;
            a0 += r[tid];
            a1 += r[tid + 256];
            a2 += r[tid + 512];
        }
    }
    g_vecs[g * BERT + tid]       = a0;
    g_vecs[g * BERT + tid + 256] = a1;
    g_vecs[g * BERT + tid + 512] = a2;
}

// ---------------------------------------------------------------------------
// Kernels 3/4: split-K GEMM partials with 8-deep register prefetch.
// grid (16 colblocks, 2 rowblocks, KSLICES=32) = 1024 CTAs, 128 threads.
// CHUNK = 24 (K=768) / 32 (K=1024).
// ---------------------------------------------------------------------------
template <int K>
__global__ __launch_bounds__(128)
void mlp_splitk_kernel(const float* __restrict__ in, const float* __restrict__ W,
                       float* __restrict__ part)
{
    constexpr int CHUNK = K / KSLICES;   // 24 or 32 (multiples of 8)
    constexpr int NB    = CHUNK / 8;     // 3 or 4 batches
    constexpr int TP    = CHUNK + 1;
    __shared__ float tile[32 * TP];

    const int tid   = threadIdx.x;
    const int q     = tid & 15;
    const int r     = tid >> 4;          // 0..7
    const int jbase = blockIdx.x * 64 + q * 4;
    const int rbase = blockIdx.y * 32;
    const int k0    = blockIdx.z * CHUNK;

    for (int e = tid; e < 32 * CHUNK; e += 128) {
        int rr = e / CHUNK;
        int cc = e - rr * CHUNK;
        tile[rr * TP + cc] = in[(size_t)(rbase + rr) * K + k0 + cc];
    }
    __syncthreads();

    float4 acc[4];
    #pragma unroll
    for (int i = 0; i < 4; i++) acc[i] = make_float4(0.f, 0.f, 0.f, 0.f);

    const float* wp = W + (size_t)k0 * H1 + jbase;
    const float* xp = tile + (r * 4) * TP;

    float4 wbuf[8];
    #pragma unroll
    for (int i = 0; i < 8; i++)
        wbuf[i] = *(const float4*)(wp + (size_t)i * H1);

    #pragma unroll
    for (int kb = 0; kb < NB; kb++) {
        float4 wnext[8];
        if (kb + 1 < NB) {
            #pragma unroll
            for (int i = 0; i < 8; i++)
                wnext[i] = *(const float4*)(wp + (size_t)((kb + 1) * 8 + i) * H1);
        }
        #pragma unroll
        for (int i = 0; i < 8; i++) {
            const int kk = kb * 8 + i;
            #pragma unroll
            for (int rr = 0; rr < 4; rr++) {
                const float xv = xp[rr * TP + kk];
                acc[rr].x += xv * wbuf[i].x;
                acc[rr].y += xv * wbuf[i].y;
                acc[rr].z += xv * wbuf[i].z;
                acc[rr].w += xv * wbuf[i].w;
            }
        }
        if (kb + 1 < NB) {
            #pragma unroll
            for (int i = 0; i < 8; i++) wbuf[i] = wnext[i];
        }
    }

    float* pb = part + (size_t)blockIdx.z * NSEG * H1 + (size_t)(rbase + r * 4) * H1 + jbase;
    #pragma unroll
    for (int i = 0; i < 4; i++)
        *(float4*)(pb + (size_t)i * H1) = acc[i];
}

// Reduce partials + bias + LeakyReLU(0.01). grid 256 (quarter-row per CTA),
// 256 threads, one scalar column each. 32 independent loads per thread.
__global__ __launch_bounds__(256)
void mlp_reduce_kernel(const float* __restrict__ b, float* __restrict__ out)
{
    const int row = blockIdx.x >> 2;
    const int col = (blockIdx.x & 3) * 256 + threadIdx.x;
    const size_t off = (size_t)row * H1 + col;

    float a = 0.f;
    #pragma unroll
    for (int z = 0; z < KSLICES; z++)
        a += g_part[(size_t)z * NSEG * H1 + off];

    a += b[col];
    out[off] = a > 0.f ? a : 0.01f * a;
}

// ---------------------------------------------------------------------------
// Kernel 5: head (64,1024)@(1024,6) + bias, sigmoid. One warp per segment.
// ---------------------------------------------------------------------------
__global__ __launch_bounds__(32)
void head_kernel(const float* __restrict__ W3, const float* __restrict__ b3,
                 float* __restrict__ out)
{
    const int g    = blockIdx.x;
    const int lane = threadIdx.x;
    float p[NCLS] = {0.f, 0.f, 0.f, 0.f, 0.f, 0.f};

    for (int k = lane; k < H1; k += 32) {
        float x = g_h2[(size_t)g * H1 + k];
        #pragma unroll
        for (int j = 0; j < NCLS; j++)
            p[j] += x * W3[k * NCLS + j];
    }
    #pragma unroll
    for (int j = 0; j < NCLS; j++) {
        #pragma unroll
        for (int o = 16; o > 0; o >>= 1)
            p[j] += __shfl_xor_sync(0xffffffffu, p[j], o);
    }
    if (lane < NCLS) {
        float v = p[lane] + b3[lane];
        out[g * NCLS + lane] = 1.f / (1.f + expf(-v));
    }
}

// ---------------------------------------------------------------------------
extern "C" void kernel_launch(void* const* d_in, const int* in_sizes, int n_in,
                              void* d_out, int out_size)
{
    (void)in_sizes; (void)n_in; (void)out_size;
    const float* emb = (const float*)d_in[0];
    const float* pos = (const float*)d_in[1];
    const float* Wa  = (const float*)d_in[2];
    const float* ba  = (const float*)d_in[3];
    const float* W1  = (const float*)d_in[4];
    const float* b1  = (const float*)d_in[5];
    const float* W2  = (const float*)d_in[6];
    const float* b2  = (const float*)d_in[7];
    const float* W3  = (const float*)d_in[8];
    const float* b3  = (const float*)d_in[9];
    const int*   seg = (const int*)d_in[10];
    float* out = (float*)d_out;

    void *p_vecs = nullptr, *p_h1 = nullptr, *p_h2 = nullptr, *p_part = nullptr;
    cudaGetSymbolAddress(&p_vecs, g_vecs);
    cudaGetSymbolAddress(&p_h1, g_h1);
    cudaGetSymbolAddress(&p_h2, g_h2);
    cudaGetSymbolAddress(&p_part, g_part);

    pool_part_kernel<<<dim3(S_SEG, 4), 256>>>(emb, pos, Wa, ba);
    pool_merge_kernel<<<S_SEG, 192>>>();
    segsum_kernel<<<NSEG, 256>>>(seg);

    mlp_splitk_kernel<BERT><<<dim3(16, 2, KSLICES), 128>>>(
        (const float*)p_vecs, W1, (float*)p_part);
    mlp_reduce_kernel<<<NSEG * 4, 256>>>(b1, (float*)p_h1);

    mlp_splitk_kernel<H1><<<dim3(16, 2, KSLICES), 128>>>(
        (const float*)p_h1, W2, (float*)p_part);
    mlp_reduce_kernel<<<NSEG * 4, 256>>>(b2, (float*)p_h2);

    head_kernel<<<NSEG, 32>>>(W3, b3, out);
}